// round 7
// baseline (speedup 1.0000x reference)
#include <cuda_runtime.h>
#include <math.h>

#define NLEV 16
#define MAX_SIZE (1u << 19)
#define P1 2654435761u
#define P2 805459861u

#define NPTS_MAX 2097152
#define KEY_BITS_DIM 6                   // res-64 Morton key
#define NBINS (1u << (3 * KEY_BITS_DIM)) // 262144 bins, ~8 pts/bin
#define SCAN_BLK 2048
#define NSCANBLKS (NBINS / SCAN_BLK)     // 128

struct LP {
    float    res[NLEV];
    unsigned mask[NLEV];
};

// Static scratch (allocation-free rule: __device__ globals)
__device__ unsigned d_hist[NBINS];      // becomes intra-block exclusive scan
__device__ unsigned d_bsums[NSCANBLKS]; // exclusive scan of block sums
__device__ float4   d_sorted[NPTS_MAX];

// ---------------- Morton key (6 bits/dim -> 18-bit key) ----------------
__device__ __forceinline__ unsigned expand_bits(unsigned v)
{
    v = (v | (v << 16)) & 0x030000FFu;
    v = (v | (v << 8))  & 0x0300F00Fu;
    v = (v | (v << 4))  & 0x030C30C3u;
    v = (v | (v << 2))  & 0x09249249u;
    return v;
}
__device__ __forceinline__ unsigned morton_key(float px, float py, float pz)
{
    unsigned ix = min(63u, (unsigned)(px * 64.0f));
    unsigned iy = min(63u, (unsigned)(py * 64.0f));
    unsigned iz = min(63u, (unsigned)(pz * 64.0f));
    return expand_bits(ix) | (expand_bits(iy) << 1) | (expand_bits(iz) << 2);
}

// Load 4 points (12 floats) with three LDG.128; p[k] = (x,y,z) of point 4t+k.
__device__ __forceinline__ void load4pts(const float4* __restrict__ X4, int t, float3 p[4])
{
    const float4 a = __ldg(&X4[3 * t + 0]);
    const float4 b = __ldg(&X4[3 * t + 1]);
    const float4 c = __ldg(&X4[3 * t + 2]);
    p[0] = make_float3(a.x, a.y, a.z);
    p[1] = make_float3(a.w, b.x, b.y);
    p[2] = make_float3(b.z, b.w, c.x);
    p[3] = make_float3(c.y, c.z, c.w);
}

// ---------------- Sort pipeline ----------------
__global__ void k_hist(const float* __restrict__ x, int n)
{
    const int t  = blockIdx.x * blockDim.x + threadIdx.x;
    const int p0 = 4 * t;
    if (p0 >= n) return;

    if (p0 + 3 < n) {
        float3 p[4];
        load4pts(reinterpret_cast<const float4*>(x), t, p);
        unsigned k0 = morton_key(p[0].x, p[0].y, p[0].z);
        unsigned k1 = morton_key(p[1].x, p[1].y, p[1].z);
        unsigned k2 = morton_key(p[2].x, p[2].y, p[2].z);
        unsigned k3 = morton_key(p[3].x, p[3].y, p[3].z);
        atomicAdd(&d_hist[k0], 1u);
        atomicAdd(&d_hist[k1], 1u);
        atomicAdd(&d_hist[k2], 1u);
        atomicAdd(&d_hist[k3], 1u);
    } else {
        for (int i = p0; i < n; ++i) {
            unsigned k = morton_key(x[3 * i], x[3 * i + 1], x[3 * i + 2]);
            atomicAdd(&d_hist[k], 1u);
        }
    }
}

// In-place Blelloch scan of d_hist per 2048-bin block; block totals to d_bsums.
__global__ void __launch_bounds__(1024) k_scan1()
{
    __shared__ unsigned s[SCAN_BLK];
    const int t = threadIdx.x;
    const unsigned base = blockIdx.x * SCAN_BLK;
    s[t] = d_hist[base + t];
    s[t + 1024] = d_hist[base + t + 1024];
    int offset = 1;
    for (int d = SCAN_BLK >> 1; d > 0; d >>= 1) {
        __syncthreads();
        if (t < d) {
            int ai = offset * (2 * t + 1) - 1;
            int bi = offset * (2 * t + 2) - 1;
            s[bi] += s[ai];
        }
        offset <<= 1;
    }
    if (t == 0) { d_bsums[blockIdx.x] = s[SCAN_BLK - 1]; s[SCAN_BLK - 1] = 0; }
    for (int d = 1; d < SCAN_BLK; d <<= 1) {
        offset >>= 1;
        __syncthreads();
        if (t < d) {
            int ai = offset * (2 * t + 1) - 1;
            int bi = offset * (2 * t + 2) - 1;
            unsigned tm = s[ai]; s[ai] = s[bi]; s[bi] += tm;
        }
    }
    __syncthreads();
    d_hist[base + t] = s[t];
    d_hist[base + t + 1024] = s[t + 1024];
}

// Exclusive scan of the 128 block sums.
__global__ void __launch_bounds__(128) k_scan2()
{
    __shared__ unsigned s[NSCANBLKS];
    const int t = threadIdx.x;
    s[t] = d_bsums[t];
    __syncthreads();
    unsigned v = s[t];
    for (int d = 1; d < NSCANBLKS; d <<= 1) {
        unsigned add = (t >= d) ? s[t - d] : 0u;
        __syncthreads();
        v += add;
        s[t] = v;
        __syncthreads();
    }
    d_bsums[t] = (t == 0) ? 0u : s[t - 1];
}

// Scatter: global offset = local scan + block-sum prefix. 4 points per thread.
__global__ void k_scatter(const float* __restrict__ x, int n)
{
    const int t  = blockIdx.x * blockDim.x + threadIdx.x;
    const int p0 = 4 * t;
    if (p0 >= n) return;

    if (p0 + 3 < n) {
        float3 p[4];
        load4pts(reinterpret_cast<const float4*>(x), t, p);
        unsigned k[4], pos[4];
#pragma unroll
        for (int j = 0; j < 4; ++j)
            k[j] = morton_key(p[j].x, p[j].y, p[j].z);
#pragma unroll
        for (int j = 0; j < 4; ++j)
            pos[j] = atomicAdd(&d_hist[k[j]], 1u);
#pragma unroll
        for (int j = 0; j < 4; ++j)
            d_sorted[pos[j] + d_bsums[k[j] >> 11]] =
                make_float4(p[j].x, p[j].y, p[j].z, __uint_as_float((unsigned)(p0 + j)));
    } else {
        for (int i = p0; i < n; ++i) {
            const float px = x[3 * i], py = x[3 * i + 1], pz = x[3 * i + 2];
            unsigned kk = morton_key(px, py, pz);
            unsigned pp = atomicAdd(&d_hist[kk], 1u) + d_bsums[kk >> 11];
            d_sorted[pp] = make_float4(px, py, pz, __uint_as_float((unsigned)i));
        }
    }
}

// ---------------- Main encode: 8 lanes/corner, 4 points/warp, sorted order ----------------
__global__ void __launch_bounds__(256)
hashgrid_kernel(const float* __restrict__ tables,
                float* __restrict__ out,
                LP lp, int n)
{
    const int lane   = threadIdx.x & 31;
    const int warpid = (blockIdx.x * (blockDim.x >> 5)) + (threadIdx.x >> 5);
    const int pt     = warpid * 4 + (lane >> 3);
    if (pt >= n) return;

    const int c  = lane & 7;
    const unsigned bx = c & 1;
    const unsigned by = (c >> 1) & 1;
    const unsigned bz = (c >> 2) & 1;

    const float4 s4 = d_sorted[pt];
    const float px = s4.x, py = s4.y, pz = s4.z;
    const unsigned oidx = __float_as_uint(s4.w);

    // Lane c keeps levels 2c and 2c+1 -> one contiguous float4 store.
    float4 r;

#pragma unroll
    for (int l = 0; l < NLEV; ++l) {
        const float    res  = lp.res[l];
        const unsigned mask = lp.mask[l];
        const float2* __restrict__ tbl =
            reinterpret_cast<const float2*>(tables) + (size_t)l * MAX_SIZE;

        const float xs = px * res, ys = py * res, zs = pz * res;
        const float fx = floorf(xs), fy = floorf(ys), fz = floorf(zs);

        const unsigned ix = (unsigned)fx + bx;
        const unsigned iy = (unsigned)fy + by;
        const unsigned iz = (unsigned)fz + bz;

        const float xf = xs - fx, yf = ys - fy, zf = zs - fz;
        const float wx = bx ? xf : 1.0f - xf;
        const float wy = by ? yf : 1.0f - yf;
        const float wz = bz ? zf : 1.0f - zf;
        const float w  = wx * wy * wz;

        const unsigned h = ix ^ (iy * P1) ^ (iz * P2);
        const float2   f = __ldg(&tbl[h & mask]);

        float vx = w * f.x;
        float vy = w * f.y;

#pragma unroll
        for (int m = 1; m < 8; m <<= 1) {
            vx += __shfl_xor_sync(0xffffffffu, vx, m);
            vy += __shfl_xor_sync(0xffffffffu, vy, m);
        }

        if ((l >> 1) == c) {
            if (l & 1) { r.z = vx; r.w = vy; }
            else       { r.x = vx; r.y = vy; }
        }
    }

    float4* o = reinterpret_cast<float4*>(out + (size_t)oidx * 32);
    o[c] = r;
}

extern "C" void kernel_launch(void* const* d_in, const int* in_sizes, int n_in,
                              void* d_out, int out_size)
{
    const float* x      = (const float*)d_in[0];
    const float* tables = (const float*)d_in[1];
    float*       out    = (float*)d_out;
    const int    n      = in_sizes[0] / 3;

    // Replicate the reference's level-resolution math EXACTLY in double precision.
    LP lp;
    const double b = exp((log(512.0) - log(16.0)) / 15.0);
    for (int l = 0; l < NLEV; ++l) {
        const double r   = floor(16.0 * pow(b, (double)l));
        const long   res = (long)r;
        long sz = res * res * res;
        if (sz > (1L << 19)) sz = (1L << 19);
        long p = 1;
        while (p < sz) p <<= 1;
        lp.res[l]  = (float)r;
        lp.mask[l] = (unsigned)(p - 1);
    }

    static void* hist_ptr = nullptr;
    if (!hist_ptr) cudaGetSymbolAddress(&hist_ptr, d_hist);

    // 1) zero histogram (1 MB)
    cudaMemsetAsync(hist_ptr, 0, NBINS * sizeof(unsigned), 0);

    // 2) histogram of 18-bit morton keys (4 pts/thread)
    const int nt4 = (n + 3) / 4;
    k_hist<<<(nt4 + 255) / 256, 256>>>(x, n);

    // 3) two-level exclusive scan (no fixup pass; bsums added at scatter)
    k_scan1<<<NSCANBLKS, 1024>>>();
    k_scan2<<<1, 128>>>();

    // 4) scatter points into morton order (orig idx in .w), 4 pts/thread
    k_scatter<<<(nt4 + 255) / 256, 256>>>(x, n);

    // 5) encode
    const int threads = 256;                 // 8 warps -> 32 points per block
    const int pts_per_block = (threads / 32) * 4;
    const int blocks = (n + pts_per_block - 1) / pts_per_block;
    hashgrid_kernel<<<blocks, threads>>>(tables, out, lp, n);
}

// round 8
// speedup vs baseline: 1.0586x; 1.0586x over previous
#include <cuda_runtime.h>
#include <math.h>

#define NLEV 16
#define MAX_SIZE (1u << 19)
#define P1 2654435761u
#define P2 805459861u

#define NPTS_MAX 2097152
#define KEY_BITS_DIM 6                   // res-64 Morton key
#define NBINS (1u << (3 * KEY_BITS_DIM)) // 262144 bins, ~8 pts/bin
#define SCAN_BLK 2048
#define NSCANBLKS (NBINS / SCAN_BLK)     // 128

struct LP {
    float    res[NLEV];
    unsigned mask[NLEV];
};

// Static scratch (allocation-free rule: __device__ globals)
__device__ unsigned d_hist[NBINS];      // becomes intra-block exclusive scan
__device__ unsigned d_bsums[NSCANBLKS]; // exclusive scan of block sums
__device__ unsigned d_perm[NPTS_MAX];   // sorted slot -> original point index (8MB, L2-resident)

// ---------------- Morton key (6 bits/dim -> 18-bit key) ----------------
__device__ __forceinline__ unsigned expand_bits(unsigned v)
{
    v = (v | (v << 16)) & 0x030000FFu;
    v = (v | (v << 8))  & 0x0300F00Fu;
    v = (v | (v << 4))  & 0x030C30C3u;
    v = (v | (v << 2))  & 0x09249249u;
    return v;
}
__device__ __forceinline__ unsigned morton_key(float px, float py, float pz)
{
    unsigned ix = min(63u, (unsigned)(px * 64.0f));
    unsigned iy = min(63u, (unsigned)(py * 64.0f));
    unsigned iz = min(63u, (unsigned)(pz * 64.0f));
    return expand_bits(ix) | (expand_bits(iy) << 1) | (expand_bits(iz) << 2);
}

// ---------------- Sort pipeline ----------------
__global__ void k_hist(const float* __restrict__ x, int n)
{
    int i = blockIdx.x * blockDim.x + threadIdx.x;
    if (i >= n) return;
    unsigned k = morton_key(x[3 * i], x[3 * i + 1], x[3 * i + 2]);
    atomicAdd(&d_hist[k], 1u);
}

// In-place Blelloch scan of d_hist per 2048-bin block; block totals to d_bsums.
__global__ void __launch_bounds__(1024) k_scan1()
{
    __shared__ unsigned s[SCAN_BLK];
    const int t = threadIdx.x;
    const unsigned base = blockIdx.x * SCAN_BLK;
    s[t] = d_hist[base + t];
    s[t + 1024] = d_hist[base + t + 1024];
    int offset = 1;
    for (int d = SCAN_BLK >> 1; d > 0; d >>= 1) {
        __syncthreads();
        if (t < d) {
            int ai = offset * (2 * t + 1) - 1;
            int bi = offset * (2 * t + 2) - 1;
            s[bi] += s[ai];
        }
        offset <<= 1;
    }
    if (t == 0) { d_bsums[blockIdx.x] = s[SCAN_BLK - 1]; s[SCAN_BLK - 1] = 0; }
    for (int d = 1; d < SCAN_BLK; d <<= 1) {
        offset >>= 1;
        __syncthreads();
        if (t < d) {
            int ai = offset * (2 * t + 1) - 1;
            int bi = offset * (2 * t + 2) - 1;
            unsigned tm = s[ai]; s[ai] = s[bi]; s[bi] += tm;
        }
    }
    __syncthreads();
    d_hist[base + t] = s[t];
    d_hist[base + t + 1024] = s[t + 1024];
}

// Exclusive scan of the 128 block sums.
__global__ void __launch_bounds__(128) k_scan2()
{
    __shared__ unsigned s[NSCANBLKS];
    const int t = threadIdx.x;
    s[t] = d_bsums[t];
    __syncthreads();
    unsigned v = s[t];
    for (int d = 1; d < NSCANBLKS; d <<= 1) {
        unsigned add = (t >= d) ? s[t - d] : 0u;
        __syncthreads();
        v += add;
        s[t] = v;
        __syncthreads();
    }
    d_bsums[t] = (t == 0) ? 0u : s[t - 1];
}

// Scatter: write ONLY the 4B original index (perm) — random writes stay in L2.
__global__ void k_scatter(const float* __restrict__ x, int n)
{
    int i = blockIdx.x * blockDim.x + threadIdx.x;
    if (i >= n) return;
    unsigned k = morton_key(x[3 * i], x[3 * i + 1], x[3 * i + 2]);
    unsigned p = atomicAdd(&d_hist[k], 1u) + d_bsums[k >> 11];
    d_perm[p] = (unsigned)i;
}

// ---------------- Main encode: 8 lanes/corner, 4 points/warp, sorted order ----------------
__global__ void __launch_bounds__(256)
hashgrid_kernel(const float* __restrict__ x,
                const float* __restrict__ tables,
                float* __restrict__ out,
                LP lp, int n)
{
    const int lane   = threadIdx.x & 31;
    const int warpid = (blockIdx.x * (blockDim.x >> 5)) + (threadIdx.x >> 5);
    const int pt     = warpid * 4 + (lane >> 3);
    if (pt >= n) return;

    const int c  = lane & 7;
    const unsigned bx = c & 1;
    const unsigned by = (c >> 1) & 1;
    const unsigned bz = (c >> 2) & 1;

    const unsigned oidx = __ldg(&d_perm[pt]);
    // Broadcast loads (all 8 lanes of the group hit the same address); x is L2-resident.
    const float px = __ldg(&x[3 * oidx + 0]);
    const float py = __ldg(&x[3 * oidx + 1]);
    const float pz = __ldg(&x[3 * oidx + 2]);

    // Lane c keeps levels 2c and 2c+1 -> one contiguous float4 store.
    float4 r;

#pragma unroll
    for (int l = 0; l < NLEV; ++l) {
        const float    res  = lp.res[l];
        const unsigned mask = lp.mask[l];
        const float2* __restrict__ tbl =
            reinterpret_cast<const float2*>(tables) + (size_t)l * MAX_SIZE;

        const float xs = px * res, ys = py * res, zs = pz * res;
        const float fx = floorf(xs), fy = floorf(ys), fz = floorf(zs);

        const unsigned ix = (unsigned)fx + bx;
        const unsigned iy = (unsigned)fy + by;
        const unsigned iz = (unsigned)fz + bz;

        const float xf = xs - fx, yf = ys - fy, zf = zs - fz;
        const float wx = bx ? xf : 1.0f - xf;
        const float wy = by ? yf : 1.0f - yf;
        const float wz = bz ? zf : 1.0f - zf;
        const float w  = wx * wy * wz;

        const unsigned h = ix ^ (iy * P1) ^ (iz * P2);
        const float2   f = __ldg(&tbl[h & mask]);

        float vx = w * f.x;
        float vy = w * f.y;

#pragma unroll
        for (int m = 1; m < 8; m <<= 1) {
            vx += __shfl_xor_sync(0xffffffffu, vx, m);
            vy += __shfl_xor_sync(0xffffffffu, vy, m);
        }

        if ((l >> 1) == c) {
            if (l & 1) { r.z = vx; r.w = vy; }
            else       { r.x = vx; r.y = vy; }
        }
    }

    float4* o = reinterpret_cast<float4*>(out + (size_t)oidx * 32);
    o[c] = r;
}

extern "C" void kernel_launch(void* const* d_in, const int* in_sizes, int n_in,
                              void* d_out, int out_size)
{
    const float* x      = (const float*)d_in[0];
    const float* tables = (const float*)d_in[1];
    float*       out    = (float*)d_out;
    const int    n      = in_sizes[0] / 3;

    // Replicate the reference's level-resolution math EXACTLY in double precision.
    LP lp;
    const double b = exp((log(512.0) - log(16.0)) / 15.0);
    for (int l = 0; l < NLEV; ++l) {
        const double r   = floor(16.0 * pow(b, (double)l));
        const long   res = (long)r;
        long sz = res * res * res;
        if (sz > (1L << 19)) sz = (1L << 19);
        long p = 1;
        while (p < sz) p <<= 1;
        lp.res[l]  = (float)r;
        lp.mask[l] = (unsigned)(p - 1);
    }

    static void* hist_ptr = nullptr;
    if (!hist_ptr) cudaGetSymbolAddress(&hist_ptr, d_hist);

    // 1) zero histogram (1 MB)
    cudaMemsetAsync(hist_ptr, 0, NBINS * sizeof(unsigned), 0);

    // 2) histogram of 18-bit morton keys
    k_hist<<<(n + 255) / 256, 256>>>(x, n);

    // 3) two-level exclusive scan (no fixup pass; bsums added at scatter)
    k_scan1<<<NSCANBLKS, 1024>>>();
    k_scan2<<<1, 128>>>();

    // 4) scatter 4B permutation indices (random writes L2-absorbed)
    k_scatter<<<(n + 255) / 256, 256>>>(x, n);

    // 5) encode
    const int threads = 256;                 // 8 warps -> 32 points per block
    const int pts_per_block = (threads / 32) * 4;
    const int blocks = (n + pts_per_block - 1) / pts_per_block;
    hashgrid_kernel<<<blocks, threads>>>(x, tables, out, lp, n);
}

// round 9
// speedup vs baseline: 1.4047x; 1.3269x over previous
#include <cuda_runtime.h>
#include <math.h>

#define NLEV 16
#define MAX_SIZE (1u << 19)
#define P1 2654435761u
#define P2 805459861u

#define NPTS_MAX 2097152
#define KEY_BITS_DIM 6                   // res-64 Morton key
#define NBINS (1u << (3 * KEY_BITS_DIM)) // 262144 bins, ~8 pts/bin
#define SCAN_BLK 2048
#define NSCANBLKS (NBINS / SCAN_BLK)     // 128

struct LP {
    float    res[NLEV];
    unsigned mask[NLEV];
};

// Static scratch (allocation-free rule: __device__ globals)
__device__ unsigned d_hist[NBINS];      // becomes intra-block exclusive scan
__device__ unsigned d_bsums[NSCANBLKS]; // exclusive scan of block sums
__device__ unsigned d_perm[NPTS_MAX];   // sorted slot -> original point index

// ---------------- Morton key (6 bits/dim -> 18-bit key) ----------------
__device__ __forceinline__ unsigned expand_bits(unsigned v)
{
    v = (v | (v << 16)) & 0x030000FFu;
    v = (v | (v << 8))  & 0x0300F00Fu;
    v = (v | (v << 4))  & 0x030C30C3u;
    v = (v | (v << 2))  & 0x09249249u;
    return v;
}
__device__ __forceinline__ unsigned morton_key(float px, float py, float pz)
{
    unsigned ix = min(63u, (unsigned)(px * 64.0f));
    unsigned iy = min(63u, (unsigned)(py * 64.0f));
    unsigned iz = min(63u, (unsigned)(pz * 64.0f));
    return expand_bits(ix) | (expand_bits(iy) << 1) | (expand_bits(iz) << 2);
}

// ---------------- Sort pipeline ----------------
__global__ void k_hist(const float* __restrict__ x, int n)
{
    int i = blockIdx.x * blockDim.x + threadIdx.x;
    if (i >= n) return;
    unsigned k = morton_key(x[3 * i], x[3 * i + 1], x[3 * i + 2]);
    atomicAdd(&d_hist[k], 1u);
}

__global__ void __launch_bounds__(1024) k_scan1()
{
    __shared__ unsigned s[SCAN_BLK];
    const int t = threadIdx.x;
    const unsigned base = blockIdx.x * SCAN_BLK;
    s[t] = d_hist[base + t];
    s[t + 1024] = d_hist[base + t + 1024];
    int offset = 1;
    for (int d = SCAN_BLK >> 1; d > 0; d >>= 1) {
        __syncthreads();
        if (t < d) {
            int ai = offset * (2 * t + 1) - 1;
            int bi = offset * (2 * t + 2) - 1;
            s[bi] += s[ai];
        }
        offset <<= 1;
    }
    if (t == 0) { d_bsums[blockIdx.x] = s[SCAN_BLK - 1]; s[SCAN_BLK - 1] = 0; }
    for (int d = 1; d < SCAN_BLK; d <<= 1) {
        offset >>= 1;
        __syncthreads();
        if (t < d) {
            int ai = offset * (2 * t + 1) - 1;
            int bi = offset * (2 * t + 2) - 1;
            unsigned tm = s[ai]; s[ai] = s[bi]; s[bi] += tm;
        }
    }
    __syncthreads();
    d_hist[base + t] = s[t];
    d_hist[base + t + 1024] = s[t + 1024];
}

__global__ void __launch_bounds__(128) k_scan2()
{
    __shared__ unsigned s[NSCANBLKS];
    const int t = threadIdx.x;
    s[t] = d_bsums[t];
    __syncthreads();
    unsigned v = s[t];
    for (int d = 1; d < NSCANBLKS; d <<= 1) {
        unsigned add = (t >= d) ? s[t - d] : 0u;
        __syncthreads();
        v += add;
        s[t] = v;
        __syncthreads();
    }
    d_bsums[t] = (t == 0) ? 0u : s[t - 1];
}

__global__ void k_scatter(const float* __restrict__ x, int n)
{
    int i = blockIdx.x * blockDim.x + threadIdx.x;
    if (i >= n) return;
    unsigned k = morton_key(x[3 * i], x[3 * i + 1], x[3 * i + 2]);
    unsigned p = atomicAdd(&d_hist[k], 1u) + d_bsums[k >> 11];
    d_perm[p] = (unsigned)i;
}

// ---------------- Main encode: 2 lanes/point, 16 points/warp ----------------
// Lane p (pair index) handles the 4 corners with by = p; bz and bx are
// unrolled in-lane (4 independent LDG.64 per level per lane). Reduction over
// corners is a single shfl_xor(1). Setup math is duplicated only 2x per point.
__global__ void __launch_bounds__(256)
hashgrid_kernel(const float* __restrict__ x,
                const float* __restrict__ tables,
                float* __restrict__ out,
                LP lp, int n)
{
    const int lane   = threadIdx.x & 31;
    const int warpid = (blockIdx.x * (blockDim.x >> 5)) + (threadIdx.x >> 5);
    const int ptraw  = warpid * 16 + (lane >> 1);
    const bool valid = ptraw < n;
    const int pt     = valid ? ptraw : (n - 1);   // clamp; lanes stay converged
    const unsigned p = lane & 1;                  // by for this lane

    const unsigned oidx = __ldg(&d_perm[pt]);
    const float px = __ldg(&x[3 * oidx + 0]);
    const float py = __ldg(&x[3 * oidx + 1]);
    const float pz = __ldg(&x[3 * oidx + 2]);

    // Lane p keeps levels [8p, 8p+8): 8 float2 = 4 float4.
    float rf[16];

#pragma unroll
    for (int l = 0; l < NLEV; ++l) {
        const float    res  = lp.res[l];
        const unsigned mask = lp.mask[l];
        const float2* __restrict__ tbl =
            reinterpret_cast<const float2*>(tables) + (size_t)l * MAX_SIZE;

        const float xs = px * res, ys = py * res, zs = pz * res;
        const float fx = floorf(xs), fy = floorf(ys), fz = floorf(zs);

        const unsigned ix = (unsigned)fx;
        const unsigned iy = (unsigned)fy + p;
        const unsigned iz = (unsigned)fz;

        const float xf = xs - fx, yf = ys - fy, zf = zs - fz;
        const float wx0 = 1.0f - xf, wx1 = xf;
        const float wy  = p ? yf : (1.0f - yf);
        const float w0  = wy * (1.0f - zf);   // bz = 0
        const float w1  = wy * zf;            // bz = 1

        const unsigned hy  = iy * P1;
        const unsigned hz0 = iz * P2;
        const unsigned hz1 = hz0 + P2;

        const unsigned ha0 = (ix       ^ hy ^ hz0) & mask;  // bx=0, bz=0
        const unsigned hb0 = ((ix + 1) ^ hy ^ hz0) & mask;  // bx=1, bz=0
        const unsigned ha1 = (ix       ^ hy ^ hz1) & mask;  // bx=0, bz=1
        const unsigned hb1 = ((ix + 1) ^ hy ^ hz1) & mask;  // bx=1, bz=1

        const float2 fa0 = __ldg(&tbl[ha0]);
        const float2 fb0 = __ldg(&tbl[hb0]);
        const float2 fa1 = __ldg(&tbl[ha1]);
        const float2 fb1 = __ldg(&tbl[hb1]);

        const float wa0 = w0 * wx0, wb0 = w0 * wx1;
        const float wa1 = w1 * wx0, wb1 = w1 * wx1;

        float vx = wa0 * fa0.x;
        float vy = wa0 * fa0.y;
        vx = fmaf(wb0, fb0.x, vx);
        vy = fmaf(wb0, fb0.y, vy);
        vx = fmaf(wa1, fa1.x, vx);
        vy = fmaf(wa1, fa1.y, vy);
        vx = fmaf(wb1, fb1.x, vx);
        vy = fmaf(wb1, fb1.y, vy);

        // sum the two y-halves
        vx += __shfl_xor_sync(0xffffffffu, vx, 1);
        vy += __shfl_xor_sync(0xffffffffu, vy, 1);

        // lane p stashes levels 8p..8p+7
        if ((l >> 3) == (int)p) {
            rf[2 * (l & 7) + 0] = vx;
            rf[2 * (l & 7) + 1] = vy;
        }
    }

    if (valid) {
        // lane p writes floats [16p, 16p+16) of this point's 32-float row.
        float4* o = reinterpret_cast<float4*>(out + (size_t)oidx * 32) + 4 * p;
        o[0] = make_float4(rf[0],  rf[1],  rf[2],  rf[3]);
        o[1] = make_float4(rf[4],  rf[5],  rf[6],  rf[7]);
        o[2] = make_float4(rf[8],  rf[9],  rf[10], rf[11]);
        o[3] = make_float4(rf[12], rf[13], rf[14], rf[15]);
    }
}

extern "C" void kernel_launch(void* const* d_in, const int* in_sizes, int n_in,
                              void* d_out, int out_size)
{
    const float* x      = (const float*)d_in[0];
    const float* tables = (const float*)d_in[1];
    float*       out    = (float*)d_out;
    const int    n      = in_sizes[0] / 3;

    // Replicate the reference's level-resolution math EXACTLY in double precision.
    LP lp;
    const double b = exp((log(512.0) - log(16.0)) / 15.0);
    for (int l = 0; l < NLEV; ++l) {
        const double r   = floor(16.0 * pow(b, (double)l));
        const long   res = (long)r;
        long sz = res * res * res;
        if (sz > (1L << 19)) sz = (1L << 19);
        long p = 1;
        while (p < sz) p <<= 1;
        lp.res[l]  = (float)r;
        lp.mask[l] = (unsigned)(p - 1);
    }

    static void* hist_ptr = nullptr;
    if (!hist_ptr) cudaGetSymbolAddress(&hist_ptr, d_hist);

    // 1) zero histogram (1 MB)
    cudaMemsetAsync(hist_ptr, 0, NBINS * sizeof(unsigned), 0);

    // 2) histogram of 18-bit morton keys
    k_hist<<<(n + 255) / 256, 256>>>(x, n);

    // 3) two-level exclusive scan
    k_scan1<<<NSCANBLKS, 1024>>>();
    k_scan2<<<1, 128>>>();

    // 4) scatter 4B permutation indices (random writes L2-absorbed)
    k_scatter<<<(n + 255) / 256, 256>>>(x, n);

    // 5) encode: 16 points per warp, 128 points per 256-thread block
    const int threads = 256;
    const int pts_per_block = (threads / 32) * 16;
    const int blocks = (n + pts_per_block - 1) / pts_per_block;
    hashgrid_kernel<<<blocks, threads>>>(x, tables, out, lp, n);
}